// round 9
// baseline (speedup 1.0000x reference)
#include <cuda_runtime.h>
#include <cuda_bf16.h>

#define S_LEN 2048
#define B_SZ  16
#define H_DIM 1024

// 8 chunk-partial slabs: g_part[ch][b][h]  (race-free -> no init kernel;
// b-half blocks write disjoint b ranges of the same slab)
__device__ float g_part[8][B_SZ * H_DIM];

// ---------------------------------------------------------------------------
// Kernel 1 v9: energy partials, batch-split for occupancy.
// Block = 128 thr (4 warps) covers (8 h-rows) x (one 128-float j-chunk)
// x (one 8-batch half). Warp tile = 2 rows x 8 b = 16 accumulators; each
// LDS.128 feeds 8 FFMAs. grid = 128 rowgroups * 8 chunks * 2 bhalves = 2048
// blocks (~55 warps/SM). 16-value butterfly (v5-proven), even lanes store.
// ---------------------------------------------------------------------------
__global__ void __launch_bounds__(128)
energy_kernel(const float* __restrict__ lds,
              const float* __restrict__ W)
{
    __shared__ float4 s_st[8 * 32];      // [b'][32 float4] for this chunk (4KB)

    const int t    = threadIdx.x;
    const int warp = t >> 5;
    const int lane = t & 31;
    const int bh   = blockIdx.x & 1;          // batch half
    const int ch   = (blockIdx.x >> 1) & 7;   // j-chunk (128 floats)
    const int rg   = blockIdx.x >> 4;         // 8-row group (0..127)
    const int row0 = rg * 8 + warp * 2;
    const int b0   = bh * 8;

    const float4* st4 = reinterpret_cast<const float4*>(lds);  // [B][256]
    const float4* W4  = reinterpret_cast<const float4*>(W);    // [H][256]

    // Stage state half-chunk: 256 float4, 128 threads -> 2 each.
    #pragma unroll
    for (int i = 0; i < 2; ++i) {
        const int v  = t + i * 128;      // 0..255
        const int bb = v >> 5;           // 0..7
        const int k  = v & 31;
        s_st[v] = st4[(size_t)(b0 + bb) * 256 + ch * 32 + k];
    }
    __syncthreads();

    const float4 w0 = W4[(size_t)row0 * 256 + ch * 32 + lane];
    const float4 w1 = W4[(size_t)(row0 + 1) * 256 + ch * 32 + lane];

    float a[16];                          // a[r*8 + b']
    #pragma unroll
    for (int bb = 0; bb < 8; ++bb) {
        const float4 s = s_st[bb * 32 + lane];
        a[bb]     = w0.x * s.x + w0.y * s.y + w0.z * s.z + w0.w * s.w;
        a[8 + bb] = w1.x * s.x + w1.y * s.y + w1.z * s.z + w1.w * s.w;
    }

    // Value-halving butterfly (16 accumulators over 32 lanes), v5 pattern:
    // steps s=16..2, then final xor-1 merge; even lane 2k holds total a[k].
    int n = 16;
    #pragma unroll
    for (int s = 16; s >= 2; s >>= 1) {
        const int  half = n >> 1;
        const bool up   = (lane & s) != 0;
        #pragma unroll
        for (int i = 0; i < half; ++i) {
            const float send = up ? a[i] : a[i + half];
            const float keep = up ? a[i + half] : a[i];
            a[i] = keep + __shfl_xor_sync(0xFFFFFFFF, send, s);
        }
        n = half;
    }
    a[0] += __shfl_xor_sync(0xFFFFFFFF, a[0], 1);

    if ((lane & 1) == 0) {
        const int idx = (lane >> 1) & 15;     // 0..15 = r*8 + b'
        const int r   = idx >> 3;
        const int bb  = idx & 7;
        g_part[ch][(size_t)(b0 + bb) * H_DIM + row0 + r] = a[0];
    }
}

// ---------------------------------------------------------------------------
// Kernel 2: scores[s][b] = sum_h enc[s][b][h] * energy[b][h]
// energy row reconstructed as sum of 8 partial slabs + bias (L2-resident).
// One block per (b, 8-row s-chunk): energy row in registers, reused 8x.
// ---------------------------------------------------------------------------
#define VPS 8
__global__ void __launch_bounds__(128, 8)
score_kernel(const float* __restrict__ enc,
             const float* __restrict__ bias,
             float* __restrict__ out)
{
    const int b  = blockIdx.x & (B_SZ - 1);
    const int s0 = (blockIdx.x >> 4) * VPS;
    const int t  = threadIdx.x;

    const float4* e4 = reinterpret_cast<const float4*>(enc);
    const float4* b4 = reinterpret_cast<const float4*>(bias);

    float4 g0 = b4[t];
    float4 g1 = b4[128 + t];
    #pragma unroll
    for (int c = 0; c < 8; ++c) {
        const float4* p4 = reinterpret_cast<const float4*>(g_part[c]);
        const float4 p0 = p4[b * (H_DIM / 4) + t];
        const float4 p1 = p4[b * (H_DIM / 4) + 128 + t];
        g0.x += p0.x; g0.y += p0.y; g0.z += p0.z; g0.w += p0.w;
        g1.x += p1.x; g1.y += p1.y; g1.z += p1.z; g1.w += p1.w;
    }

    float acc[VPS];
    #pragma unroll
    for (int i = 0; i < VPS; ++i) {
        const size_t row = ((size_t)(s0 + i) * B_SZ + b) * (H_DIM / 4);
        const float4 a0 = e4[row + t];
        const float4 a1 = e4[row + 128 + t];
        acc[i] = a0.x * g0.x + a0.y * g0.y + a0.z * g0.z + a0.w * g0.w
               + a1.x * g1.x + a1.y * g1.y + a1.z * g1.z + a1.w * g1.w;
    }

    #pragma unroll
    for (int i = 0; i < VPS; ++i)
        #pragma unroll
        for (int off = 16; off > 0; off >>= 1)
            acc[i] += __shfl_xor_sync(0xFFFFFFFF, acc[i], off);

    __shared__ float red[4][VPS];
    const int warp = t >> 5;
    const int lane = t & 31;
    if (lane == 0) {
        #pragma unroll
        for (int i = 0; i < VPS; ++i)
            red[warp][i] = acc[i];
    }
    __syncthreads();
    if (t < VPS)
        out[(size_t)(s0 + t) * B_SZ + b] =
            red[0][t] + red[1][t] + red[2][t] + red[3][t];
}

// ---------------------------------------------------------------------------
// Kernel 3: softmax over S per column b. 16 blocks x 1024 threads,
// 2 values/thread in registers, two block-wide reductions.
// ---------------------------------------------------------------------------
__global__ void __launch_bounds__(1024)
softmax_kernel(float* __restrict__ out)
{
    const int b = blockIdx.x;
    const int t = threadIdx.x;

    float v0 = out[(size_t)t * B_SZ + b];
    float v1 = out[(size_t)(t + 1024) * B_SZ + b];

    __shared__ float sm[32];
    const int warp = t >> 5, lane = t & 31;

    float mx = fmaxf(v0, v1);
    #pragma unroll
    for (int off = 16; off > 0; off >>= 1)
        mx = fmaxf(mx, __shfl_xor_sync(0xFFFFFFFF, mx, off));
    if (lane == 0) sm[warp] = mx;
    __syncthreads();
    if (warp == 0) {
        float m = sm[lane];
        #pragma unroll
        for (int off = 16; off > 0; off >>= 1)
            m = fmaxf(m, __shfl_xor_sync(0xFFFFFFFF, m, off));
        if (lane == 0) sm[0] = m;
    }
    __syncthreads();
    mx = sm[0];
    __syncthreads();

    v0 = __expf(v0 - mx);
    v1 = __expf(v1 - mx);
    float sum = v0 + v1;
    #pragma unroll
    for (int off = 16; off > 0; off >>= 1)
        sum += __shfl_xor_sync(0xFFFFFFFF, sum, off);
    if (lane == 0) sm[warp] = sum;
    __syncthreads();
    if (warp == 0) {
        float s = sm[lane];
        #pragma unroll
        for (int off = 16; off > 0; off >>= 1)
            s += __shfl_xor_sync(0xFFFFFFFF, s, off);
        if (lane == 0) sm[0] = s;
    }
    __syncthreads();
    const float inv = 1.0f / sm[0];

    out[(size_t)t * B_SZ + b]          = v0 * inv;
    out[(size_t)(t + 1024) * B_SZ + b] = v1 * inv;
}

// ---------------------------------------------------------------------------
extern "C" void kernel_launch(void* const* d_in, const int* in_sizes, int n_in,
                              void* d_out, int out_size)
{
    const float* enc  = (const float*)d_in[0];  // [S,B,H]
    const float* lds  = (const float*)d_in[1];  // [2,1,B,H]
    const float* W    = (const float*)d_in[2];  // [H,H]
    const float* bias = (const float*)d_in[3];  // [H]
    float* out = (float*)d_out;                 // [1,1,S,B] == [S,B]

    energy_kernel<<<2048, 128>>>(lds, W);
    score_kernel<<<(S_LEN / VPS) * B_SZ, 128>>>(enc, bias, out);
    softmax_kernel<<<B_SZ, 1024>>>(out);
}